// round 4
// baseline (speedup 1.0000x reference)
#include <cuda_runtime.h>
#include <math_constants.h>

#define BD   4
#define SEQ  2048
#define EMB  1024
#define NH   16
#define HD   64
#define MROWS (BD*SEQ)   // 8192

// Scratch (allocation-free: __device__ globals)
static __device__ float g_q  [(size_t)BD*NH*SEQ*HD];   // (B,H,S,D)
static __device__ float g_k  [(size_t)BD*NH*SEQ*HD];
static __device__ float g_v  [(size_t)BD*NH*SEQ*HD];
static __device__ float g_ctx[(size_t)BD*SEQ*EMB];     // (B,S,E)

// ---------------------------------------------------------------------------
// C[m,n] = sum_k A[m,k]*Bw[n,k] + bias[n]   (torch Linear: x @ W^T + b)
// A: MROWS x EMB row-major, Bw: EMB x EMB row-major, K=N=EMB.
// EPI=0: C row-major (M,N).  EPI=1: head-split write into (B,H,S,D).
// Double-buffered smem + register prefetch: one __syncthreads per k-tile,
// global-load latency hidden under the 512-FMA compute phase.
// ---------------------------------------------------------------------------
template <int EPI>
__global__ void __launch_bounds__(256, 2) gemm_bias_nt(
    const float* __restrict__ A, const float* __restrict__ Bw,
    const float* __restrict__ bias, float* __restrict__ C)
{
    constexpr int K = EMB, N = EMB;
    __shared__ float As[2][8][128];
    __shared__ float Bs[2][8][128];

    const int t  = threadIdx.x;
    const int bm = blockIdx.y * 128;
    const int bn = blockIdx.x * 128;

    const int lr = t >> 1;          // 0..127
    const int lc = (t & 1) * 4;     // 0 or 4
    const float* Ap = A  + (size_t)(bm + lr) * K + lc;
    const float* Bp = Bw + (size_t)(bn + lr) * K + lc;

    const int tr = (t >> 4) * 8;    // 0..120 step 8
    const int tc = (t & 15) * 8;

    float acc[8][8] = {};

    // prologue: stage k-tile 0 into buffer 0
    {
        float4 av = *(const float4*)(Ap);
        float4 bv = *(const float4*)(Bp);
        As[0][lc+0][lr] = av.x; As[0][lc+1][lr] = av.y;
        As[0][lc+2][lr] = av.z; As[0][lc+3][lr] = av.w;
        Bs[0][lc+0][lr] = bv.x; Bs[0][lc+1][lr] = bv.y;
        Bs[0][lc+2][lr] = bv.z; Bs[0][lc+3][lr] = bv.w;
    }
    __syncthreads();

    int buf = 0;
    for (int k0 = 8; k0 <= K; k0 += 8) {
        // prefetch next k-tile into registers (latency hidden by compute below)
        float4 av, bv;
        if (k0 < K) {
            av = *(const float4*)(Ap + k0);
            bv = *(const float4*)(Bp + k0);
        }

        // compute current tile from smem[buf]
        #pragma unroll
        for (int k = 0; k < 8; k++) {
            float ra[8], rb[8];
            *(float4*)&ra[0] = *(const float4*)&As[buf][k][tr];
            *(float4*)&ra[4] = *(const float4*)&As[buf][k][tr + 4];
            *(float4*)&rb[0] = *(const float4*)&Bs[buf][k][tc];
            *(float4*)&rb[4] = *(const float4*)&Bs[buf][k][tc + 4];
            #pragma unroll
            for (int i = 0; i < 8; i++)
                #pragma unroll
                for (int j = 0; j < 8; j++)
                    acc[i][j] = fmaf(ra[i], rb[j], acc[i][j]);
        }

        // stage next tile into the other buffer; single barrier per iteration
        if (k0 < K) {
            const int nb = buf ^ 1;
            As[nb][lc+0][lr] = av.x; As[nb][lc+1][lr] = av.y;
            As[nb][lc+2][lr] = av.z; As[nb][lc+3][lr] = av.w;
            Bs[nb][lc+0][lr] = bv.x; Bs[nb][lc+1][lr] = bv.y;
            Bs[nb][lc+2][lr] = bv.z; Bs[nb][lc+3][lr] = bv.w;
            __syncthreads();
            buf = nb;
        }
    }

    #pragma unroll
    for (int i = 0; i < 8; i++) {
        const int m = bm + tr + i;
        #pragma unroll
        for (int j = 0; j < 8; j += 4) {
            const int n = bn + tc + j;
            float4 r;
            r.x = acc[i][j+0] + bias[n+0];
            r.y = acc[i][j+1] + bias[n+1];
            r.z = acc[i][j+2] + bias[n+2];
            r.w = acc[i][j+3] + bias[n+3];
            if (EPI == 0) {
                *(float4*)&C[(size_t)m * N + n] = r;
            } else {
                const int b_ = m >> 11, s_ = m & (SEQ - 1);
                const int h_ = n >> 6,  d_ = n & (HD - 1);
                *(float4*)&C[((((size_t)b_ * NH + h_) * SEQ + s_) << 6) + d_] = r;
            }
        }
    }
}

// ---------------------------------------------------------------------------
// fp32 flash attention, causal. Q/K/V in (B*H, S, D). ctx out in (B, S, E).
// Block: 64 query rows x full head. 256 threads; thread (tr,tc) owns a 4x4
// score tile; the 16 threads sharing a row group reduce via width-16 shuffles.
// Q is pre-scaled by 1/sqrt(HD)=0.125 at load (exact power-of-two scale).
// KP holds K^T[d][c] during scores, is re-used as P[r][c] for the PV GEMM.
// Static smem = 3 * 16KB = 48KB.
// ---------------------------------------------------------------------------
__global__ void __launch_bounds__(256) flash_attn(
    const float* __restrict__ Q, const float* __restrict__ K,
    const float* __restrict__ V, float* __restrict__ ctx)
{
    __shared__ float Qs[64][64];
    __shared__ float KP[64][64];
    __shared__ float Vs[64][64];

    const int t  = threadIdx.x;
    const int qt = blockIdx.x;          // query tile
    const int bh = blockIdx.y;          // batch*head
    const int b_ = bh >> 4, h_ = bh & (NH - 1);

    const int lr = t >> 2;              // load row 0..63
    const int lc = (t & 3) * 16;        // load col base

    const float* Qg = Q + ((size_t)bh * SEQ + (size_t)qt * 64) * HD;
    #pragma unroll
    for (int v = 0; v < 4; v++) {
        float4 x = *(const float4*)(Qg + lr*HD + lc + v*4);
        x.x *= 0.125f; x.y *= 0.125f; x.z *= 0.125f; x.w *= 0.125f;
        *(float4*)&Qs[lr][lc + v*4] = x;
    }

    const int tr = t >> 4;              // 0..15
    const int tc = t & 15;              // 0..15
    const int r0 = tr * 4;

    float m_i[4], l_i[4], o[4][4];
    #pragma unroll
    for (int i = 0; i < 4; i++) {
        m_i[i] = -CUDART_INF_F; l_i[i] = 0.f;
        #pragma unroll
        for (int j = 0; j < 4; j++) o[i][j] = 0.f;
    }

    for (int jt = 0; jt <= qt; jt++) {
        const float* Kg = K + ((size_t)bh * SEQ + (size_t)jt * 64) * HD;
        const float* Vg = V + ((size_t)bh * SEQ + (size_t)jt * 64) * HD;

        __syncthreads();                        // prev-iter consumers done
        #pragma unroll
        for (int v = 0; v < 4; v++) {
            float4 x = *(const float4*)(Kg + lr*HD + lc + v*4);
            KP[lc + v*4 + 0][lr] = x.x;         // K^T: [d][c]
            KP[lc + v*4 + 1][lr] = x.y;
            KP[lc + v*4 + 2][lr] = x.z;
            KP[lc + v*4 + 3][lr] = x.w;
            *(float4*)&Vs[lr][lc + v*4] = *(const float4*)(Vg + lr*HD + lc + v*4);
        }
        __syncthreads();

        // S = (Q/8) * K^T  (4x4 per thread)
        float s[4][4] = {};
        #pragma unroll 8
        for (int d = 0; d < 64; d++) {
            float4 kv = *(const float4*)&KP[d][tc * 4];
            float q0 = Qs[r0+0][d], q1 = Qs[r0+1][d];
            float q2 = Qs[r0+2][d], q3 = Qs[r0+3][d];
            s[0][0] = fmaf(q0, kv.x, s[0][0]); s[0][1] = fmaf(q0, kv.y, s[0][1]);
            s[0][2] = fmaf(q0, kv.z, s[0][2]); s[0][3] = fmaf(q0, kv.w, s[0][3]);
            s[1][0] = fmaf(q1, kv.x, s[1][0]); s[1][1] = fmaf(q1, kv.y, s[1][1]);
            s[1][2] = fmaf(q1, kv.z, s[1][2]); s[1][3] = fmaf(q1, kv.w, s[1][3]);
            s[2][0] = fmaf(q2, kv.x, s[2][0]); s[2][1] = fmaf(q2, kv.y, s[2][1]);
            s[2][2] = fmaf(q2, kv.z, s[2][2]); s[2][3] = fmaf(q2, kv.w, s[2][3]);
            s[3][0] = fmaf(q3, kv.x, s[3][0]); s[3][1] = fmaf(q3, kv.y, s[3][1]);
            s[3][2] = fmaf(q3, kv.z, s[3][2]); s[3][3] = fmaf(q3, kv.w, s[3][3]);
        }

        // causal mask + online softmax (scores already scaled)
        const int rg0 = qt * 64 + r0;
        const int cg0 = jt * 64 + tc * 4;
        #pragma unroll
        for (int i = 0; i < 4; i++) {
            float rowm = -CUDART_INF_F;
            #pragma unroll
            for (int jj = 0; jj < 4; jj++) {
                float v_ = s[i][jj];
                if (cg0 + jj > rg0 + i) v_ = -CUDART_INF_F;
                s[i][jj] = v_;
                rowm = fmaxf(rowm, v_);
            }
            rowm = fmaxf(rowm, __shfl_xor_sync(0xffffffffu, rowm, 8, 16));
            rowm = fmaxf(rowm, __shfl_xor_sync(0xffffffffu, rowm, 4, 16));
            rowm = fmaxf(rowm, __shfl_xor_sync(0xffffffffu, rowm, 2, 16));
            rowm = fmaxf(rowm, __shfl_xor_sync(0xffffffffu, rowm, 1, 16));
            const float mnew = fmaxf(m_i[i], rowm);
            const float resc = __expf(m_i[i] - mnew);
            m_i[i] = mnew;
            float rs = 0.f;
            #pragma unroll
            for (int jj = 0; jj < 4; jj++) {
                s[i][jj] = __expf(s[i][jj] - mnew);
                rs += s[i][jj];
            }
            rs += __shfl_xor_sync(0xffffffffu, rs, 8, 16);
            rs += __shfl_xor_sync(0xffffffffu, rs, 4, 16);
            rs += __shfl_xor_sync(0xffffffffu, rs, 2, 16);
            rs += __shfl_xor_sync(0xffffffffu, rs, 1, 16);
            l_i[i] = l_i[i] * resc + rs;
            #pragma unroll
            for (int jj = 0; jj < 4; jj++) o[i][jj] *= resc;
        }

        __syncthreads();                        // everyone done reading KP as K^T
        float (*Ps)[64] = KP;                   // alias as P[r][c]
        #pragma unroll
        for (int i = 0; i < 4; i++)
            *(float4*)&Ps[r0 + i][tc * 4] =
                make_float4(s[i][0], s[i][1], s[i][2], s[i][3]);
        __syncthreads();

        // O += P * V  (4 rows x 4 head-dims per thread)
        #pragma unroll 8
        for (int c = 0; c < 64; c++) {
            float4 vv = *(const float4*)&Vs[c][tc * 4];
            float p0 = Ps[r0+0][c], p1 = Ps[r0+1][c];
            float p2 = Ps[r0+2][c], p3 = Ps[r0+3][c];
            o[0][0] = fmaf(p0, vv.x, o[0][0]); o[0][1] = fmaf(p0, vv.y, o[0][1]);
            o[0][2] = fmaf(p0, vv.z, o[0][2]); o[0][3] = fmaf(p0, vv.w, o[0][3]);
            o[1][0] = fmaf(p1, vv.x, o[1][0]); o[1][1] = fmaf(p1, vv.y, o[1][1]);
            o[1][2] = fmaf(p1, vv.z, o[1][2]); o[1][3] = fmaf(p1, vv.w, o[1][3]);
            o[2][0] = fmaf(p2, vv.x, o[2][0]); o[2][1] = fmaf(p2, vv.y, o[2][1]);
            o[2][2] = fmaf(p2, vv.z, o[2][2]); o[2][3] = fmaf(p2, vv.w, o[2][3]);
            o[3][0] = fmaf(p3, vv.x, o[3][0]); o[3][1] = fmaf(p3, vv.y, o[3][1]);
            o[3][2] = fmaf(p3, vv.z, o[3][2]); o[3][3] = fmaf(p3, vv.w, o[3][3]);
        }
    }

    // epilogue: normalize, write ctx in (B,S,E)
    #pragma unroll
    for (int i = 0; i < 4; i++) {
        const float inv = 1.f / l_i[i];
        const int s_ = qt * 64 + r0 + i;
        float4 r;
        r.x = o[i][0] * inv; r.y = o[i][1] * inv;
        r.z = o[i][2] * inv; r.w = o[i][3] * inv;
        *(float4*)&ctx[((size_t)b_ * SEQ + s_) * EMB + h_ * HD + tc * 4] = r;
    }
}

// ---------------------------------------------------------------------------
extern "C" void kernel_launch(void* const* d_in, const int* in_sizes, int n_in,
                              void* d_out, int out_size)
{
    (void)in_sizes; (void)n_in; (void)out_size;
    const float* query = (const float*)d_in[0];
    const float* key   = (const float*)d_in[1];
    const float* value = (const float*)d_in[2];
    // d_in[3] = attn_mask (causal triu) — baked into the flash kernel
    const float* q_w = (const float*)d_in[4];
    const float* q_b = (const float*)d_in[5];
    const float* k_w = (const float*)d_in[6];
    const float* k_b = (const float*)d_in[7];
    const float* v_w = (const float*)d_in[8];
    const float* v_b = (const float*)d_in[9];
    const float* o_w = (const float*)d_in[10];
    const float* o_b = (const float*)d_in[11];

    float *gq, *gk, *gv, *gctx;
    cudaGetSymbolAddress((void**)&gq,   g_q);
    cudaGetSymbolAddress((void**)&gk,   g_k);
    cudaGetSymbolAddress((void**)&gv,   g_v);
    cudaGetSymbolAddress((void**)&gctx, g_ctx);

    const dim3 gg(EMB / 128, MROWS / 128);   // (8, 64)
    gemm_bias_nt<1><<<gg, 256>>>(query, q_w, q_b, gq);
    gemm_bias_nt<1><<<gg, 256>>>(key,   k_w, k_b, gk);
    gemm_bias_nt<1><<<gg, 256>>>(value, v_w, v_b, gv);

    flash_attn<<<dim3(SEQ / 64, BD * NH), 256>>>(gq, gk, gv, gctx);

    gemm_bias_nt<0><<<gg, 256>>>(gctx, o_w, o_b, (float*)d_out);
}

// round 6
// speedup vs baseline: 1.5439x; 1.5439x over previous
#include <cuda_runtime.h>
#include <math_constants.h>
#include <stdint.h>

#define BD   4
#define SEQ  2048
#define EMB  1024
#define NH   16
#define HD   64
#define MROWS (BD*SEQ)   // 8192
#define SW   136         // smem row stride in words: banks = 8*(k%4)+ (m%8) pattern, conflict-free frags

// Scratch (allocation-free: __device__ globals)
static __device__ float g_q  [(size_t)BD*NH*SEQ*HD];   // (B,H,S,D)
static __device__ float g_k  [(size_t)BD*NH*SEQ*HD];
static __device__ float g_v  [(size_t)BD*NH*SEQ*HD];
static __device__ float g_ctx[(size_t)BD*SEQ*EMB];     // (B,S,E)

__device__ __forceinline__ uint32_t f2tf32(float x) {
    uint32_t r;
    asm("cvt.rna.tf32.f32 %0, %1;" : "=r"(r) : "f"(x));
    return r;
}
// D = A(16x8, row) * B(8x8, col) + D, tf32 inputs, f32 accum. sm_80+ PTX.
__device__ __forceinline__ void mma_tf32(float* c, const uint32_t* a, const uint32_t* b) {
    asm volatile(
        "mma.sync.aligned.m16n8k8.row.col.f32.tf32.tf32.f32 "
        "{%0,%1,%2,%3}, {%4,%5,%6,%7}, {%8,%9}, {%0,%1,%2,%3};\n"
        : "+f"(c[0]), "+f"(c[1]), "+f"(c[2]), "+f"(c[3])
        : "r"(a[0]), "r"(a[1]), "r"(a[2]), "r"(a[3]), "r"(b[0]), "r"(b[1]));
}

// ===========================================================================
// tf32 mma.sync GEMM: C[m,n] = sum_k A[m,k]*Bw[n,k] + bias[n]
// A: MROWS x 1024 row-major, Bw: 1024 x 1024 row-major (torch W, so B is
// k-col-major exactly as mma's .col operand wants).
// CTA: 256 thr, tile 128x128, K-chunk 16, double-buffered smem (k-major,
// stride SW=136 words -> conflict-free fragment LDS).
// Warp grid 2(m) x 4(n): each warp owns 64x32 via 4x4 m16n8 tiles.
// EPI=0: row-major out.  EPI=1: head-split (B,H,S,D) out.
// ===========================================================================
template <int EPI>
__global__ void __launch_bounds__(256) gemm_tf32_mma(
    const float* __restrict__ A, const float* __restrict__ Bw,
    const float* __restrict__ bias, float* __restrict__ C)
{
    __shared__ uint32_t sA[2][16 * SW];   // 8704 B each buffer
    __shared__ uint32_t sB[2][16 * SW];   // total 34816 B

    const int t  = threadIdx.x;
    const int bm = blockIdx.y * 128;
    const int bn = blockIdx.x * 128;

    // loader mapping: 2 threads per row, 8 floats each (2 float4)
    const int lm = t >> 1;            // 0..127
    const int kq = (t & 1) * 8;       // 0 or 8
    const float* Ap = A  + (size_t)(bm + lm) * EMB + kq;
    const float* Bp = Bw + (size_t)(bn + lm) * EMB + kq;

    // mma mapping
    const int wid  = t >> 5, lane = t & 31;
    const int q    = lane & 3, g = lane >> 2;
    const int wm   = (wid & 1) * 64;
    const int wn   = (wid >> 1) * 32;

    float acc[4][4][4] = {};

    // stage chunk (already in regs) into smem buffer with cvt to tf32
    auto stage = [&](int buf, float4 a0, float4 a1, float4 b0, float4 b1) {
        uint32_t* pa = &sA[buf][lm];
        uint32_t* pb = &sB[buf][lm];
        pa[(kq+0)*SW] = f2tf32(a0.x); pa[(kq+1)*SW] = f2tf32(a0.y);
        pa[(kq+2)*SW] = f2tf32(a0.z); pa[(kq+3)*SW] = f2tf32(a0.w);
        pa[(kq+4)*SW] = f2tf32(a1.x); pa[(kq+5)*SW] = f2tf32(a1.y);
        pa[(kq+6)*SW] = f2tf32(a1.z); pa[(kq+7)*SW] = f2tf32(a1.w);
        pb[(kq+0)*SW] = f2tf32(b0.x); pb[(kq+1)*SW] = f2tf32(b0.y);
        pb[(kq+2)*SW] = f2tf32(b0.z); pb[(kq+3)*SW] = f2tf32(b0.w);
        pb[(kq+4)*SW] = f2tf32(b1.x); pb[(kq+5)*SW] = f2tf32(b1.y);
        pb[(kq+6)*SW] = f2tf32(b1.z); pb[(kq+7)*SW] = f2tf32(b1.w);
    };

    // prologue: chunk 0
    {
        float4 a0 = *(const float4*)(Ap + 0), a1 = *(const float4*)(Ap + 4);
        float4 b0 = *(const float4*)(Bp + 0), b1 = *(const float4*)(Bp + 4);
        stage(0, a0, a1, b0, b1);
    }
    __syncthreads();

    int buf = 0;
    for (int c = 0; c < EMB / 16; ++c) {
        float4 na0, na1, nb0, nb1;
        const bool more = (c + 1) < EMB / 16;
        if (more) {
            const int k0 = (c + 1) * 16;
            na0 = *(const float4*)(Ap + k0 + 0); na1 = *(const float4*)(Ap + k0 + 4);
            nb0 = *(const float4*)(Bp + k0 + 0); nb1 = *(const float4*)(Bp + k0 + 4);
        }

        // compute: 2 k-steps of 8
        #pragma unroll
        for (int ks = 0; ks < 16; ks += 8) {
            const uint32_t* paq  = &sA[buf][(ks + q    ) * SW];
            const uint32_t* paq4 = &sA[buf][(ks + q + 4) * SW];
            const uint32_t* pbq  = &sB[buf][(ks + q    ) * SW];
            const uint32_t* pbq4 = &sB[buf][(ks + q + 4) * SW];

            uint32_t af[4][4], bf[4][2];
            #pragma unroll
            for (int tm = 0; tm < 4; ++tm) {
                const int mo = wm + tm * 16 + g;
                af[tm][0] = paq [mo];     af[tm][1] = paq [mo + 8];
                af[tm][2] = paq4[mo];     af[tm][3] = paq4[mo + 8];
            }
            #pragma unroll
            for (int tn = 0; tn < 4; ++tn) {
                const int no = wn + tn * 8 + g;
                bf[tn][0] = pbq [no];     bf[tn][1] = pbq4[no];
            }
            #pragma unroll
            for (int tm = 0; tm < 4; ++tm)
                #pragma unroll
                for (int tn = 0; tn < 4; ++tn)
                    mma_tf32(acc[tm][tn], af[tm], bf[tn]);
        }

        if (more) {
            stage(buf ^ 1, na0, na1, nb0, nb1);
            __syncthreads();
            buf ^= 1;
        }
    }

    // epilogue: c0,c1 -> row g, cols 2q,2q+1 ; c2,c3 -> row g+8
    #pragma unroll
    for (int tm = 0; tm < 4; ++tm) {
        const int r0 = bm + wm + tm * 16 + g;
        #pragma unroll
        for (int tn = 0; tn < 4; ++tn) {
            const int n  = bn + wn + tn * 8 + 2 * q;
            const float bx = bias[n], by = bias[n + 1];
            float2 v0 = make_float2(acc[tm][tn][0] + bx, acc[tm][tn][1] + by);
            float2 v1 = make_float2(acc[tm][tn][2] + bx, acc[tm][tn][3] + by);
            if (EPI == 0) {
                *(float2*)&C[(size_t)r0      * EMB + n] = v0;
                *(float2*)&C[(size_t)(r0+8)  * EMB + n] = v1;
            } else {
                const int h_ = n >> 6, d_ = n & (HD - 1);
                {
                    const int b_ = r0 >> 11, s_ = r0 & (SEQ - 1);
                    *(float2*)&C[((((size_t)b_ * NH + h_) * SEQ + s_) << 6) + d_] = v0;
                }
                {
                    const int r1 = r0 + 8;
                    const int b_ = r1 >> 11, s_ = r1 & (SEQ - 1);
                    *(float2*)&C[((((size_t)b_ * NH + h_) * SEQ + s_) << 6) + d_] = v1;
                }
            }
        }
    }
}

// ---------------------------------------------------------------------------
// fp32 flash attention, causal (unchanged from the passing R4 kernel).
// ---------------------------------------------------------------------------
__global__ void __launch_bounds__(256) flash_attn(
    const float* __restrict__ Q, const float* __restrict__ K,
    const float* __restrict__ V, float* __restrict__ ctx)
{
    __shared__ float Qs[64][64];
    __shared__ float KP[64][64];
    __shared__ float Vs[64][64];

    const int t  = threadIdx.x;
    const int qt = blockIdx.x;          // query tile
    const int bh = blockIdx.y;          // batch*head
    const int b_ = bh >> 4, h_ = bh & (NH - 1);

    const int lr = t >> 2;              // load row 0..63
    const int lc = (t & 3) * 16;        // load col base

    const float* Qg = Q + ((size_t)bh * SEQ + (size_t)qt * 64) * HD;
    #pragma unroll
    for (int v = 0; v < 4; v++) {
        float4 x = *(const float4*)(Qg + lr*HD + lc + v*4);
        x.x *= 0.125f; x.y *= 0.125f; x.z *= 0.125f; x.w *= 0.125f;
        *(float4*)&Qs[lr][lc + v*4] = x;
    }

    const int tr = t >> 4;              // 0..15
    const int tc = t & 15;              // 0..15
    const int r0 = tr * 4;

    float m_i[4], l_i[4], o[4][4];
    #pragma unroll
    for (int i = 0; i < 4; i++) {
        m_i[i] = -CUDART_INF_F; l_i[i] = 0.f;
        #pragma unroll
        for (int j = 0; j < 4; j++) o[i][j] = 0.f;
    }

    for (int jt = 0; jt <= qt; jt++) {
        const float* Kg = K + ((size_t)bh * SEQ + (size_t)jt * 64) * HD;
        const float* Vg = V + ((size_t)bh * SEQ + (size_t)jt * 64) * HD;

        __syncthreads();                        // prev-iter consumers done
        #pragma unroll
        for (int v = 0; v < 4; v++) {
            float4 x = *(const float4*)(Kg + lr*HD + lc + v*4);
            KP[lc + v*4 + 0][lr] = x.x;         // K^T: [d][c]
            KP[lc + v*4 + 1][lr] = x.y;
            KP[lc + v*4 + 2][lr] = x.z;
            KP[lc + v*4 + 3][lr] = x.w;
            *(float4*)&Vs[lr][lc + v*4] = *(const float4*)(Vg + lr*HD + lc + v*4);
        }
        __syncthreads();

        // S = (Q/8) * K^T  (4x4 per thread)
        float s[4][4] = {};
        #pragma unroll 8
        for (int d = 0; d < 64; d++) {
            float4 kv = *(const float4*)&KP[d][tc * 4];
            float q0 = Qs[r0+0][d], q1 = Qs[r0+1][d];
            float q2 = Qs[r0+2][d], q3 = Qs[r0+3][d];
            s[0][0] = fmaf(q0, kv.x, s[0][0]); s[0][1] = fmaf(q0, kv.y, s[0][1]);
            s[0][2] = fmaf(q0, kv.z, s[0][2]); s[0][3] = fmaf(q0, kv.w, s[0][3]);
            s[1][0] = fmaf(q1, kv.x, s[1][0]); s[1][1] = fmaf(q1, kv.y, s[1][1]);
            s[1][2] = fmaf(q1, kv.z, s[1][2]); s[1][3] = fmaf(q1, kv.w, s[1][3]);
            s[2][0] = fmaf(q2, kv.x, s[2][0]); s[2][1] = fmaf(q2, kv.y, s[2][1]);
            s[2][2] = fmaf(q2, kv.z, s[2][2]); s[2][3] = fmaf(q2, kv.w, s[2][3]);
            s[3][0] = fmaf(q3, kv.x, s[3][0]); s[3][1] = fmaf(q3, kv.y, s[3][1]);
            s[3][2] = fmaf(q3, kv.z, s[3][2]); s[3][3] = fmaf(q3, kv.w, s[3][3]);
        }

        // causal mask + online softmax (scores already scaled)
        const int rg0 = qt * 64 + r0;
        const int cg0 = jt * 64 + tc * 4;
        #pragma unroll
        for (int i = 0; i < 4; i++) {
            float rowm = -CUDART_INF_F;
            #pragma unroll
            for (int jj = 0; jj < 4; jj++) {
                float v_ = s[i][jj];
                if (cg0 + jj > rg0 + i) v_ = -CUDART_INF_F;
                s[i][jj] = v_;
                rowm = fmaxf(rowm, v_);
            }
            rowm = fmaxf(rowm, __shfl_xor_sync(0xffffffffu, rowm, 8, 16));
            rowm = fmaxf(rowm, __shfl_xor_sync(0xffffffffu, rowm, 4, 16));
            rowm = fmaxf(rowm, __shfl_xor_sync(0xffffffffu, rowm, 2, 16));
            rowm = fmaxf(rowm, __shfl_xor_sync(0xffffffffu, rowm, 1, 16));
            const float mnew = fmaxf(m_i[i], rowm);
            const float resc = __expf(m_i[i] - mnew);
            m_i[i] = mnew;
            float rs = 0.f;
            #pragma unroll
            for (int jj = 0; jj < 4; jj++) {
                s[i][jj] = __expf(s[i][jj] - mnew);
                rs += s[i][jj];
            }
            rs += __shfl_xor_sync(0xffffffffu, rs, 8, 16);
            rs += __shfl_xor_sync(0xffffffffu, rs, 4, 16);
            rs += __shfl_xor_sync(0xffffffffu, rs, 2, 16);
            rs += __shfl_xor_sync(0xffffffffu, rs, 1, 16);
            l_i[i] = l_i[i] * resc + rs;
            #pragma unroll
            for (int jj = 0; jj < 4; jj++) o[i][jj] *= resc;
        }

        __syncthreads();                        // everyone done reading KP as K^T
        float (*Ps)[64] = KP;                   // alias as P[r][c]
        #pragma unroll
        for (int i = 0; i < 4; i++)
            *(float4*)&Ps[r0 + i][tc * 4] =
                make_float4(s[i][0], s[i][1], s[i][2], s[i][3]);
        __syncthreads();

        // O += P * V  (4 rows x 4 head-dims per thread)
        #pragma unroll 8
        for (int c = 0; c < 64; c++) {
            float4 vv = *(const float4*)&Vs[c][tc * 4];
            float p0 = Ps[r0+0][c], p1 = Ps[r0+1][c];
            float p2 = Ps[r0+2][c], p3 = Ps[r0+3][c];
            o[0][0] = fmaf(p0, vv.x, o[0][0]); o[0][1] = fmaf(p0, vv.y, o[0][1]);
            o[0][2] = fmaf(p0, vv.z, o[0][2]); o[0][3] = fmaf(p0, vv.w, o[0][3]);
            o[1][0] = fmaf(p1, vv.x, o[1][0]); o[1][1] = fmaf(p1, vv.y, o[1][1]);
            o[1][2] = fmaf(p1, vv.z, o[1][2]); o[1][3] = fmaf(p1, vv.w, o[1][3]);
            o[2][0] = fmaf(p2, vv.x, o[2][0]); o[2][1] = fmaf(p2, vv.y, o[2][1]);
            o[2][2] = fmaf(p2, vv.z, o[2][2]); o[2][3] = fmaf(p2, vv.w, o[2][3]);
            o[3][0] = fmaf(p3, vv.x, o[3][0]); o[3][1] = fmaf(p3, vv.y, o[3][1]);
            o[3][2] = fmaf(p3, vv.z, o[3][2]); o[3][3] = fmaf(p3, vv.w, o[3][3]);
        }
    }

    // epilogue: normalize, write ctx in (B,S,E)
    #pragma unroll
    for (int i = 0; i < 4; i++) {
        const float inv = 1.f / l_i[i];
        const int s_ = qt * 64 + r0 + i;
        float4 r;
        r.x = o[i][0] * inv; r.y = o[i][1] * inv;
        r.z = o[i][2] * inv; r.w = o[i][3] * inv;
        *(float4*)&ctx[((size_t)b_ * SEQ + s_) * EMB + h_ * HD + tc * 4] = r;
    }
}

// ---------------------------------------------------------------------------
extern "C" void kernel_launch(void* const* d_in, const int* in_sizes, int n_in,
                              void* d_out, int out_size)
{
    (void)in_sizes; (void)n_in; (void)out_size;
    const float* query = (const float*)d_in[0];
    const float* key   = (const float*)d_in[1];
    const float* value = (const float*)d_in[2];
    // d_in[3] = attn_mask (causal triu) — baked into the flash kernel
    const float* q_w = (const float*)d_in[4];
    const float* q_b = (const float*)d_in[5];
    const float* k_w = (const float*)d_in[6];
    const float* k_b = (const float*)d_in[7];
    const float* v_w = (const float*)d_in[8];
    const float* v_b = (const float*)d_in[9];
    const float* o_w = (const float*)d_in[10];
    const float* o_b = (const float*)d_in[11];

    float *gq, *gk, *gv, *gctx;
    cudaGetSymbolAddress((void**)&gq,   g_q);
    cudaGetSymbolAddress((void**)&gk,   g_k);
    cudaGetSymbolAddress((void**)&gv,   g_v);
    cudaGetSymbolAddress((void**)&gctx, g_ctx);

    const dim3 gg(EMB / 128, MROWS / 128);   // (8, 64)
    gemm_tf32_mma<1><<<gg, 256>>>(query, q_w, q_b, gq);
    gemm_tf32_mma<1><<<gg, 256>>>(key,   k_w, k_b, gk);
    gemm_tf32_mma<1><<<gg, 256>>>(value, v_w, v_b, gv);

    flash_attn<<<dim3(SEQ / 64, BD * NH), 256>>>(gq, gk, gv, gctx);

    gemm_tf32_mma<0><<<gg, 256>>>(gctx, o_w, o_b, (float*)d_out);
}